// round 2
// baseline (speedup 1.0000x reference)
#include <cuda_runtime.h>

#define BS 4
#define H0 64
#define W0 64
#define L0 4096   /* H0*W0 */
#define L1 4096
#define NM 20000  /* number of candidate matches */
#define ANUM 64   /* anchors per batch */

#define THREADS 1024
#define COPY_BLOCKS 296                     /* 2 blocks/SM * 148 SMs */
#define N4 ((size_t)BS * L0 * L1 / 4)       /* 16,777,216 float4 */

__global__ void __launch_bounds__(THREADS) fused_kernel(
    const float* __restrict__ conf_matrix,
    const float* __restrict__ mconf,
    const int* __restrict__ b_ids,
    const int* __restrict__ i_ids,
    const int* __restrict__ j_ids,
    float* __restrict__ out) {

    // ---- shared state (only used by the 4 anchor blocks) ----
    __shared__ int   s_winner[L0];   // per-cell last-write-wins match index
    __shared__ float s_conf[L0];
    __shared__ int   s_sel_i[ANUM];
    __shared__ int   s_sel_j[ANUM];
    __shared__ int   s_warp[32];
    __shared__ int   s_total;

    const int t = threadIdx.x;

    if (blockIdx.x < COPY_BLOCKS) {
        // ================= conf_matrix passthrough copy =================
        const float4* __restrict__ src = (const float4*)conf_matrix;
        float4* __restrict__ dst = (float4*)(out + (size_t)BS * ANUM * 4);
        const size_t stride = (size_t)COPY_BLOCKS * THREADS;
        size_t i = (size_t)blockIdx.x * THREADS + t;
        // unroll-4 main loop: 4 outstanding 128-bit loads per thread
        for (; i + 3 * stride < N4; i += 4 * stride) {
            float4 a0 = src[i];
            float4 a1 = src[i + stride];
            float4 a2 = src[i + 2 * stride];
            float4 a3 = src[i + 3 * stride];
            dst[i]              = a0;
            dst[i + stride]     = a1;
            dst[i + 2 * stride] = a2;
            dst[i + 3 * stride] = a3;
        }
        for (; i < N4; i += stride) dst[i] = src[i];
        return;
    }

    // ================= anchors for batch b =================
    const int b = blockIdx.x - COPY_BLOCKS;

    // init winners
    for (int c = t; c < L0; c += THREADS) s_winner[c] = -1;
    __syncthreads();

    // scatter: last update (largest m) wins -> atomicMax on match index
    for (int m = t; m < NM; m += THREADS) {
        if (b_ids[m] == b) atomicMax(&s_winner[i_ids[m]], m);
    }
    __syncthreads();

    // gather confidences
    for (int c = t; c < L0; c += THREADS) {
        int w = s_winner[c];
        s_conf[c] = (w >= 0) ? __ldg(&mconf[w]) : 0.0f;
    }
    __syncthreads();

    // NMS over 4 raster-contiguous cells per thread:
    // survivor <=> v > 0 and v >= right, down, diag neighbors (pad=0)
    const int base = t * 4;
    int lmask = 0, cnt = 0;
#pragma unroll
    for (int k = 0; k < 4; k++) {
        int c = base + k;
        int h = c >> 6, w = c & 63;
        float v = s_conf[c];
        bool ok = v > 0.0f;
        if (ok && (w + 1 < W0))                 ok = (v >= s_conf[c + 1]);
        if (ok && (h + 1 < H0))                 ok = (v >= s_conf[c + 64]);
        if (ok && (w + 1 < W0) && (h + 1 < H0)) ok = (v >= s_conf[c + 65]);
        if (ok) { lmask |= (1 << k); cnt++; }
    }

    // block-wide exclusive scan (thread order == raster order)
    const int lane = t & 31, warp = t >> 5;
    int incl = cnt;
#pragma unroll
    for (int d = 1; d < 32; d <<= 1) {
        int n = __shfl_up_sync(0xffffffffu, incl, d);
        if (lane >= d) incl += n;
    }
    if (lane == 31) s_warp[warp] = incl;
    __syncthreads();
    if (warp == 0) {
        int v = s_warp[lane];
#pragma unroll
        for (int d = 1; d < 32; d <<= 1) {
            int n = __shfl_up_sync(0xffffffffu, v, d);
            if (lane >= d) v += n;
        }
        s_warp[lane] = v;
        if (lane == 31) s_total = v;
    }
    __syncthreads();
    int excl = incl - cnt + (warp > 0 ? s_warp[warp - 1] : 0);

    // record the first ANUM survivors (raster order) with their j targets
    if (lmask) {
        int r = excl;
#pragma unroll
        for (int k = 0; k < 4; k++) {
            if (lmask & (1 << k)) {
                if (r < ANUM) {
                    int c = base + k;
                    s_sel_i[r] = c;
                    s_sel_j[r] = __ldg(&j_ids[s_winner[c]]);
                }
                r++;
            }
        }
    }
    __syncthreads();

    // emit anchors [ANUM, 2, 2]
    if (t < ANUM) {
        int total = s_total;
        float4 res;
        if (total == 0) {
            res = make_float4(0.0f, 0.0f, 0.0f, 0.0f);
        } else {
            int idx = t % total;          // t<64: always indexes a stored survivor
            int i_sel = s_sel_i[idx];
            int j_sel = s_sel_j[idx];
            res.x = (float)(i_sel >> 6);
            res.y = (float)(i_sel & 63);
            res.z = (float)(j_sel >> 6);
            res.w = (float)(j_sel & 63);
        }
        reinterpret_cast<float4*>(out)[b * ANUM + t] = res;
    }
}

extern "C" void kernel_launch(void* const* d_in, const int* in_sizes, int n_in,
                              void* d_out, int out_size) {
    const float* conf_matrix = (const float*)d_in[0];
    const float* mconf       = (const float*)d_in[1];
    const int*   b_ids       = (const int*)d_in[2];
    const int*   i_ids       = (const int*)d_in[3];
    const int*   j_ids       = (const int*)d_in[4];
    float* out = (float*)d_out;

    fused_kernel<<<COPY_BLOCKS + BS, THREADS>>>(conf_matrix, mconf, b_ids,
                                                i_ids, j_ids, out);
}

// round 4
// speedup vs baseline: 1.0560x; 1.0560x over previous
#include <cuda_runtime.h>

#define BS 4
#define H0 64
#define W0 64
#define L0 4096   /* H0*W0 */
#define L1 4096
#define NM 20000  /* number of candidate matches */
#define ANUM 64   /* anchors per batch */

#define THREADS 1024
#define COPY_BLOCKS 292                     /* + 4 anchor blocks = 296 = 2*148 SMs */
#define N4 ((size_t)BS * L0 * L1 / 4)       /* 16,777,216 float4 */

__global__ void __launch_bounds__(THREADS, 2) fused_kernel(
    const float* __restrict__ conf_matrix,
    const float* __restrict__ mconf,
    const int* __restrict__ b_ids,
    const int* __restrict__ i_ids,
    const int* __restrict__ j_ids,
    float* __restrict__ out) {

    // ---- shared state (only used by the 4 anchor blocks) ----
    __shared__ int   s_winner[L0];   // per-cell last-write-wins match index
    __shared__ float s_conf[L0];
    __shared__ int   s_sel_i[ANUM];
    __shared__ int   s_sel_j[ANUM];
    __shared__ int   s_warp[32];
    __shared__ int   s_total;

    const int t = threadIdx.x;

    if (blockIdx.x < COPY_BLOCKS) {
        // ================= conf_matrix passthrough copy =================
        const float4* __restrict__ src = (const float4*)conf_matrix;
        float4* __restrict__ dst = (float4*)(out + (size_t)BS * ANUM * 4);
        const size_t stride = (size_t)COPY_BLOCKS * THREADS;
        size_t i = (size_t)blockIdx.x * THREADS + t;
        // unroll-2 (8 data regs) -> fits 32-reg budget for 2 blocks/SM;
        // 64 warps/SM x 2 outstanding 128b loads supplies the MLP.
        for (; i + stride < N4; i += 2 * stride) {
            float4 a0 = __ldcs(&src[i]);
            float4 a1 = __ldcs(&src[i + stride]);
            __stcs(&dst[i], a0);
            __stcs(&dst[i + stride], a1);
        }
        if (i < N4) __stcs(&dst[i], __ldcs(&src[i]));
        return;
    }

    // ================= anchors for batch b =================
    const int b = blockIdx.x - COPY_BLOCKS;

    // init winners
    for (int c = t; c < L0; c += THREADS) s_winner[c] = -1;
    __syncthreads();

    // scatter: last update (largest m) wins -> atomicMax on match index
    for (int m = t; m < NM; m += THREADS) {
        if (b_ids[m] == b) atomicMax(&s_winner[i_ids[m]], m);
    }
    __syncthreads();

    // gather confidences
    for (int c = t; c < L0; c += THREADS) {
        int w = s_winner[c];
        s_conf[c] = (w >= 0) ? __ldg(&mconf[w]) : 0.0f;
    }
    __syncthreads();

    // NMS over 4 raster-contiguous cells per thread:
    // survivor <=> v > 0 and v >= right, down, diag neighbors (pad=0)
    const int base = t * 4;
    int lmask = 0, cnt = 0;
#pragma unroll
    for (int k = 0; k < 4; k++) {
        int c = base + k;
        int h = c >> 6, w = c & 63;
        float v = s_conf[c];
        bool ok = v > 0.0f;
        if (ok && (w + 1 < W0))                 ok = (v >= s_conf[c + 1]);
        if (ok && (h + 1 < H0))                 ok = (v >= s_conf[c + 64]);
        if (ok && (w + 1 < W0) && (h + 1 < H0)) ok = (v >= s_conf[c + 65]);
        if (ok) { lmask |= (1 << k); cnt++; }
    }

    // block-wide exclusive scan (thread order == raster order)
    const int lane = t & 31, warp = t >> 5;
    int incl = cnt;
#pragma unroll
    for (int d = 1; d < 32; d <<= 1) {
        int n = __shfl_up_sync(0xffffffffu, incl, d);
        if (lane >= d) incl += n;
    }
    if (lane == 31) s_warp[warp] = incl;
    __syncthreads();
    if (warp == 0) {
        int v = s_warp[lane];
#pragma unroll
        for (int d = 1; d < 32; d <<= 1) {
            int n = __shfl_up_sync(0xffffffffu, v, d);
            if (lane >= d) v += n;
        }
        s_warp[lane] = v;
        if (lane == 31) s_total = v;
    }
    __syncthreads();
    int excl = incl - cnt + (warp > 0 ? s_warp[warp - 1] : 0);

    // record the first ANUM survivors (raster order) with their j targets
    if (lmask) {
        int r = excl;
#pragma unroll
        for (int k = 0; k < 4; k++) {
            if (lmask & (1 << k)) {
                if (r < ANUM) {
                    int c = base + k;
                    s_sel_i[r] = c;
                    s_sel_j[r] = __ldg(&j_ids[s_winner[c]]);
                }
                r++;
            }
        }
    }
    __syncthreads();

    // emit anchors [ANUM, 2, 2]
    if (t < ANUM) {
        int total = s_total;
        float4 res;
        if (total == 0) {
            res = make_float4(0.0f, 0.0f, 0.0f, 0.0f);
        } else {
            int idx = t % total;          // t<64: always indexes a stored survivor
            int i_sel = s_sel_i[idx];
            int j_sel = s_sel_j[idx];
            res.x = (float)(i_sel >> 6);
            res.y = (float)(i_sel & 63);
            res.z = (float)(j_sel >> 6);
            res.w = (float)(j_sel & 63);
        }
        reinterpret_cast<float4*>(out)[b * ANUM + t] = res;
    }
}

extern "C" void kernel_launch(void* const* d_in, const int* in_sizes, int n_in,
                              void* d_out, int out_size) {
    const float* conf_matrix = (const float*)d_in[0];
    const float* mconf       = (const float*)d_in[1];
    const int*   b_ids       = (const int*)d_in[2];
    const int*   i_ids       = (const int*)d_in[3];
    const int*   j_ids       = (const int*)d_in[4];
    float* out = (float*)d_out;

    fused_kernel<<<COPY_BLOCKS + BS, THREADS>>>(conf_matrix, mconf, b_ids,
                                                i_ids, j_ids, out);
}

// round 6
// speedup vs baseline: 1.0639x; 1.0074x over previous
#include <cuda_runtime.h>

#define BS 4
#define H0 64
#define W0 64
#define L0 4096   /* H0*W0 */
#define L1 4096
#define NM 20000  /* number of candidate matches */
#define ANUM 64   /* anchors per batch */

#define THREADS 1024
#define COPY_BLOCKS 292                     /* + 4 anchor blocks = 296 = 2*148 SMs */
#define N4 ((size_t)BS * L0 * L1 / 4)       /* 16,777,216 float4 */

__global__ void __launch_bounds__(THREADS, 2) fused_kernel(
    const float* __restrict__ conf_matrix,
    const float* __restrict__ mconf,
    const int* __restrict__ b_ids,
    const int* __restrict__ i_ids,
    const int* __restrict__ j_ids,
    float* __restrict__ out) {

    // ---- shared state (only used by the 4 anchor blocks) ----
    __shared__ int   s_winner[L0];   // per-cell last-write-wins match index
    __shared__ float s_conf[L0];
    __shared__ int   s_sel_i[ANUM];
    __shared__ int   s_sel_j[ANUM];
    __shared__ int   s_warp[32];
    __shared__ int   s_total;

    const int t = threadIdx.x;

    if (blockIdx.x < COPY_BLOCKS) {
        // ================= conf_matrix passthrough copy =================
        // Strided unroll-4: each warp instruction covers 512B contiguous
        // (4 lines/wavefront, optimal), and the 4 loads per thread share one
        // address register via immediate offsets (stride*16B = 4.78MB < 8MB
        // imm range) -> ~24 regs, 4 outstanding LDG.128 per thread.
        const float4* __restrict__ src = (const float4*)conf_matrix;
        float4* __restrict__ dst = (float4*)(out + (size_t)BS * ANUM * 4);
        const size_t stride = (size_t)COPY_BLOCKS * THREADS;  // 299008
        size_t i = (size_t)blockIdx.x * THREADS + t;
        for (; i + 3 * stride < N4; i += 4 * stride) {
            float4 a0 = __ldcs(&src[i]);
            float4 a1 = __ldcs(&src[i + stride]);
            float4 a2 = __ldcs(&src[i + 2 * stride]);
            float4 a3 = __ldcs(&src[i + 3 * stride]);
            __stcs(&dst[i],              a0);
            __stcs(&dst[i + stride],     a1);
            __stcs(&dst[i + 2 * stride], a2);
            __stcs(&dst[i + 3 * stride], a3);
        }
        for (; i < N4; i += stride) __stcs(&dst[i], __ldcs(&src[i]));
        return;
    }

    // ================= anchors for batch b =================
    const int b = blockIdx.x - COPY_BLOCKS;

    // init winners
    for (int c = t; c < L0; c += THREADS) s_winner[c] = -1;
    __syncthreads();

    // scatter: last update (largest m) wins -> atomicMax on match index
    for (int m = t; m < NM; m += THREADS) {
        if (b_ids[m] == b) atomicMax(&s_winner[i_ids[m]], m);
    }
    __syncthreads();

    // gather confidences
    for (int c = t; c < L0; c += THREADS) {
        int w = s_winner[c];
        s_conf[c] = (w >= 0) ? __ldg(&mconf[w]) : 0.0f;
    }
    __syncthreads();

    // NMS over 4 raster-contiguous cells per thread:
    // survivor <=> v > 0 and v >= right, down, diag neighbors (pad=0)
    const int base = t * 4;
    int lmask = 0, cnt = 0;
#pragma unroll
    for (int k = 0; k < 4; k++) {
        int c = base + k;
        int h = c >> 6, w = c & 63;
        float v = s_conf[c];
        bool ok = v > 0.0f;
        if (ok && (w + 1 < W0))                 ok = (v >= s_conf[c + 1]);
        if (ok && (h + 1 < H0))                 ok = (v >= s_conf[c + 64]);
        if (ok && (w + 1 < W0) && (h + 1 < H0)) ok = (v >= s_conf[c + 65]);
        if (ok) { lmask |= (1 << k); cnt++; }
    }

    // block-wide exclusive scan (thread order == raster order)
    const int lane = t & 31, warp = t >> 5;
    int incl = cnt;
#pragma unroll
    for (int d = 1; d < 32; d <<= 1) {
        int n = __shfl_up_sync(0xffffffffu, incl, d);
        if (lane >= d) incl += n;
    }
    if (lane == 31) s_warp[warp] = incl;
    __syncthreads();
    if (warp == 0) {
        int v = s_warp[lane];
#pragma unroll
        for (int d = 1; d < 32; d <<= 1) {
            int n = __shfl_up_sync(0xffffffffu, v, d);
            if (lane >= d) v += n;
        }
        s_warp[lane] = v;
        if (lane == 31) s_total = v;
    }
    __syncthreads();
    int excl = incl - cnt + (warp > 0 ? s_warp[warp - 1] : 0);

    // record the first ANUM survivors (raster order) with their j targets
    if (lmask) {
        int r = excl;
#pragma unroll
        for (int k = 0; k < 4; k++) {
            if (lmask & (1 << k)) {
                if (r < ANUM) {
                    int c = base + k;
                    s_sel_i[r] = c;
                    s_sel_j[r] = __ldg(&j_ids[s_winner[c]]);
                }
                r++;
            }
        }
    }
    __syncthreads();

    // emit anchors [ANUM, 2, 2]
    if (t < ANUM) {
        int total = s_total;
        float4 res;
        if (total == 0) {
            res = make_float4(0.0f, 0.0f, 0.0f, 0.0f);
        } else {
            int idx = t % total;          // t<64: always indexes a stored survivor
            int i_sel = s_sel_i[idx];
            int j_sel = s_sel_j[idx];
            res.x = (float)(i_sel >> 6);
            res.y = (float)(i_sel & 63);
            res.z = (float)(j_sel >> 6);
            res.w = (float)(j_sel & 63);
        }
        reinterpret_cast<float4*>(out)[b * ANUM + t] = res;
    }
}

extern "C" void kernel_launch(void* const* d_in, const int* in_sizes, int n_in,
                              void* d_out, int out_size) {
    const float* conf_matrix = (const float*)d_in[0];
    const float* mconf       = (const float*)d_in[1];
    const int*   b_ids       = (const int*)d_in[2];
    const int*   i_ids       = (const int*)d_in[3];
    const int*   j_ids       = (const int*)d_in[4];
    float* out = (float*)d_out;

    fused_kernel<<<COPY_BLOCKS + BS, THREADS>>>(conf_matrix, mconf, b_ids,
                                                i_ids, j_ids, out);
}

// round 7
// speedup vs baseline: 1.1360x; 1.0678x over previous
#include <cuda_runtime.h>
#include <cstdint>

#define BS 4
#define H0 64
#define W0 64
#define L0 4096   /* H0*W0 */
#define L1 4096
#define NM 20000  /* number of candidate matches */
#define ANUM 64   /* anchors per batch */

#define THREADS 1024
#define COPY_BLOCKS 296                       /* 2/SM on 148 SMs */
#define TOTAL_BYTES ((size_t)BS * L0 * L1 * 4)  /* 268435456 */
#define CHUNK 8192
#define NCHUNKS (TOTAL_BYTES / CHUNK)         /* 32768 */
#define CPB 111                               /* ceil(32768/296) */
#define DEPTH 5
#define LOOKAHEAD 3

__device__ __forceinline__ uint32_t smem_u32(const void* p) {
    uint32_t a;
    asm("{ .reg .u64 t; cvta.to.shared.u64 t, %1; cvt.u32.u64 %0, t; }"
        : "=r"(a) : "l"(p));
    return a;
}

__global__ void __launch_bounds__(THREADS) fused_kernel(
    const float* __restrict__ conf_matrix,
    const float* __restrict__ mconf,
    const int* __restrict__ b_ids,
    const int* __restrict__ i_ids,
    const int* __restrict__ j_ids,
    float* __restrict__ out) {

    // 40KB staging ring for the copy path; overlaid by the anchor arrays.
    __shared__ __align__(1024) unsigned char s_raw[DEPTH * CHUNK];
    __shared__ __align__(8) uint64_t s_mbar[DEPTH];

    const int t = threadIdx.x;

    if (blockIdx.x < COPY_BLOCKS) {
        // ========== conf_matrix passthrough: TMA bulk-copy pipeline ==========
        if (t != 0) return;   // single-thread TMA orchestration

        const size_t start = (size_t)blockIdx.x * CPB;
        size_t end = start + CPB;
        if (end > NCHUNKS) end = NCHUNKS;
        if (start >= end) return;
        const int n = (int)(end - start);

        const char* srcg = (const char*)conf_matrix + start * CHUNK;
        char* dstg = (char*)(out + (size_t)BS * ANUM * 4) + start * CHUNK;

        // init barriers (count=1: tx-based completion)
        uint32_t mb[DEPTH];
#pragma unroll
        for (int s = 0; s < DEPTH; s++) {
            mb[s] = smem_u32(&s_mbar[s]);
            asm volatile("mbarrier.init.shared.b64 [%0], 1;" :: "r"(mb[s]) : "memory");
        }
        asm volatile("fence.proxy.async.shared::cta;" ::: "memory");

        uint32_t stg[DEPTH];
#pragma unroll
        for (int s = 0; s < DEPTH; s++) stg[s] = smem_u32(&s_raw[s * CHUNK]);

        // prime: LOOKAHEAD loads in flight
        const int pre = (n < LOOKAHEAD) ? n : LOOKAHEAD;
        for (int k = 0; k < pre; k++) {
            asm volatile("mbarrier.arrive.expect_tx.shared.b64 _, [%0], %1;"
                         :: "r"(mb[k]), "r"((uint32_t)CHUNK) : "memory");
            asm volatile("cp.async.bulk.shared::cta.global.mbarrier::complete_tx::bytes "
                         "[%0], [%1], %2, [%3];"
                         :: "r"(stg[k]), "l"(srcg + (size_t)k * CHUNK),
                            "r"((uint32_t)CHUNK), "r"(mb[k]) : "memory");
        }

        for (int c = 0; c < n; c++) {
            const int s = c % DEPTH;
            const uint32_t ph = (uint32_t)((c / DEPTH) & 1);
            // wait load of chunk c
            asm volatile(
                "{\n\t"
                ".reg .pred P;\n\t"
                "WL_%=:\n\t"
                "mbarrier.try_wait.parity.shared.b64 P, [%0], %1, 0x989680;\n\t"
                "@P bra.uni WD_%=;\n\t"
                "bra.uni WL_%=;\n\t"
                "WD_%=:\n\t"
                "}"
                :: "r"(mb[s]), "r"(ph) : "memory");
            // store chunk c smem -> gmem
            asm volatile("cp.async.bulk.global.shared::cta.bulk_group [%0], [%1], %2;"
                         :: "l"(dstg + (size_t)c * CHUNK), "r"(stg[s]),
                            "r"((uint32_t)CHUNK) : "memory");
            asm volatile("cp.async.bulk.commit_group;" ::: "memory");

            const int nk = c + LOOKAHEAD;
            if (nk < n) {
                const int s2 = nk % DEPTH;
                // stage s2 previously held chunk nk-DEPTH whose store was
                // committed DEPTH-LOOKAHEAD=2 commits ago -> wait_group.read 2
                asm volatile("cp.async.bulk.wait_group.read 2;" ::: "memory");
                asm volatile("mbarrier.arrive.expect_tx.shared.b64 _, [%0], %1;"
                             :: "r"(mb[s2]), "r"((uint32_t)CHUNK) : "memory");
                asm volatile("cp.async.bulk.shared::cta.global.mbarrier::complete_tx::bytes "
                             "[%0], [%1], %2, [%3];"
                             :: "r"(stg[s2]), "l"(srcg + (size_t)nk * CHUNK),
                                "r"((uint32_t)CHUNK), "r"(mb[s2]) : "memory");
            }
        }
        asm volatile("cp.async.bulk.wait_group.read 0;" ::: "memory");
        return;
    }

    // ================= anchors for batch b (overlaid smem) =================
    const int b = blockIdx.x - COPY_BLOCKS;

    int*   s_winner = (int*)s_raw;                       // [L0]  16KB
    float* s_conf   = (float*)(s_raw + 16384);           // [L0]  16KB
    int*   s_sel_i  = (int*)(s_raw + 32768);             // [ANUM]
    int*   s_sel_j  = (int*)(s_raw + 32768 + 256);       // [ANUM]
    int*   s_warp   = (int*)(s_raw + 32768 + 512);       // [32]
    int*   s_total  = (int*)(s_raw + 32768 + 640);       // [1]

    for (int c = t; c < L0; c += THREADS) s_winner[c] = -1;
    __syncthreads();

    // scatter: last update (largest m) wins -> atomicMax on match index
    for (int m = t; m < NM; m += THREADS) {
        if (b_ids[m] == b) atomicMax(&s_winner[i_ids[m]], m);
    }
    __syncthreads();

    for (int c = t; c < L0; c += THREADS) {
        int w = s_winner[c];
        s_conf[c] = (w >= 0) ? __ldg(&mconf[w]) : 0.0f;
    }
    __syncthreads();

    // NMS over 4 raster-contiguous cells per thread
    const int base = t * 4;
    int lmask = 0, cnt = 0;
#pragma unroll
    for (int k = 0; k < 4; k++) {
        int c = base + k;
        int h = c >> 6, w = c & 63;
        float v = s_conf[c];
        bool ok = v > 0.0f;
        if (ok && (w + 1 < W0))                 ok = (v >= s_conf[c + 1]);
        if (ok && (h + 1 < H0))                 ok = (v >= s_conf[c + 64]);
        if (ok && (w + 1 < W0) && (h + 1 < H0)) ok = (v >= s_conf[c + 65]);
        if (ok) { lmask |= (1 << k); cnt++; }
    }

    // block-wide exclusive scan (thread order == raster order)
    const int lane = t & 31, warp = t >> 5;
    int incl = cnt;
#pragma unroll
    for (int d = 1; d < 32; d <<= 1) {
        int x = __shfl_up_sync(0xffffffffu, incl, d);
        if (lane >= d) incl += x;
    }
    if (lane == 31) s_warp[warp] = incl;
    __syncthreads();
    if (warp == 0) {
        int v = s_warp[lane];
#pragma unroll
        for (int d = 1; d < 32; d <<= 1) {
            int x = __shfl_up_sync(0xffffffffu, v, d);
            if (lane >= d) v += x;
        }
        s_warp[lane] = v;
        if (lane == 31) *s_total = v;
    }
    __syncthreads();
    int excl = incl - cnt + (warp > 0 ? s_warp[warp - 1] : 0);

    if (lmask) {
        int r = excl;
#pragma unroll
        for (int k = 0; k < 4; k++) {
            if (lmask & (1 << k)) {
                if (r < ANUM) {
                    int c = base + k;
                    s_sel_i[r] = c;
                    s_sel_j[r] = __ldg(&j_ids[s_winner[c]]);
                }
                r++;
            }
        }
    }
    __syncthreads();

    if (t < ANUM) {
        int total = *s_total;
        float4 res;
        if (total == 0) {
            res = make_float4(0.0f, 0.0f, 0.0f, 0.0f);
        } else {
            int idx = t % total;
            int i_sel = s_sel_i[idx];
            int j_sel = s_sel_j[idx];
            res.x = (float)(i_sel >> 6);
            res.y = (float)(i_sel & 63);
            res.z = (float)(j_sel >> 6);
            res.w = (float)(j_sel & 63);
        }
        reinterpret_cast<float4*>(out)[b * ANUM + t] = res;
    }
}

extern "C" void kernel_launch(void* const* d_in, const int* in_sizes, int n_in,
                              void* d_out, int out_size) {
    const float* conf_matrix = (const float*)d_in[0];
    const float* mconf       = (const float*)d_in[1];
    const int*   b_ids       = (const int*)d_in[2];
    const int*   i_ids       = (const int*)d_in[3];
    const int*   j_ids       = (const int*)d_in[4];
    float* out = (float*)d_out;

    fused_kernel<<<COPY_BLOCKS + BS, THREADS>>>(conf_matrix, mconf, b_ids,
                                                i_ids, j_ids, out);
}